// round 1
// baseline (speedup 1.0000x reference)
#include <cuda_runtime.h>
#include <cstdint>

#define NB 32
#define NP 64
#define NL 64
#define NV 32000

// scratch (no allocations allowed)
__device__ float g_sumS[NB * NP];
__device__ int   g_m[NB * NP];
__device__ float g_loss[NB * NP];

// ---------------------------------------------------------------------------
// Kernel A: per-batch Myers bit-parallel edit distance + argmin truth set.
// 1 warp per batch. Lane l owns DP rows {l, l+32}.
// Produces per (b,r): m = #distinct target vocab at argmin positions,
//                     sumS = sum of outputs[b,r,v] over those distinct v.
// ---------------------------------------------------------------------------
__global__ void __launch_bounds__(32) dp_kernel(
    const float* __restrict__ outputs,
    const int*   __restrict__ outsym,
    const int*   __restrict__ targets,
    const unsigned char* __restrict__ mask)
{
    __shared__ int   tgt_s[64];
    __shared__ int   sym_s[64];
    __shared__ float gsh[64 * 65];   // gsh[r*65 + c] = outputs[b, r, targets[b,c]]

    const int b = blockIdx.x;
    const int l = threadIdx.x;

    const int t_lo = targets[b * 64 + l];
    const int t_hi = targets[b * 64 + 32 + l];
    tgt_s[l]      = t_lo;
    tgt_s[32 + l] = t_hi;
    sym_s[l]      = outsym[b * 64 + l];
    sym_s[32 + l] = outsym[b * 64 + 32 + l];

    const unsigned mml = __ballot_sync(0xffffffffu, mask[b * 64 + l] != 0);
    const unsigned mmh = __ballot_sync(0xffffffffu, mask[b * 64 + 32 + l] != 0);
    const unsigned long long mm = ((unsigned long long)mmh << 32) | (unsigned long long)mml;

    // Gather table: 128 independent loads per lane, latency-hidden by MLP.
    #pragma unroll 4
    for (int r = 0; r < 64; r++) {
        const float* rowp = outputs + (size_t)(b * 64 + r) * NV;
        gsh[r * 65 + l]      = rowp[t_lo];
        gsh[r * 65 + 32 + l] = rowp[t_hi];
    }
    __syncwarp();

    // Myers bit-vector DP. Pattern = targets[0..62] (63 bits), text = output
    // symbols. After row r: VP/VN bit k = dist[r][k+1] - dist[r][k].
    unsigned long long VP = 0x7FFFFFFFFFFFFFFFull;  // row 0: dist = arange
    unsigned long long VN = 0ull;
    unsigned long long vp0 = VP, vn0 = VN;          // lane 0 snapshot = row 0
    unsigned long long vp1 = 0ull, vn1 = 0ull;

    for (int r = 1; r < 64; r++) {
        const int s = sym_s[r - 1];
        const unsigned eql = __ballot_sync(0xffffffffu, t_lo == s);
        const unsigned eqh = __ballot_sync(0xffffffffu, t_hi == s) & 0x7FFFFFFFu;
        const unsigned long long Eq = ((unsigned long long)eqh << 32) | (unsigned long long)eql;

        const unsigned long long X  = Eq | VN;
        const unsigned long long D0 = ((VP + (X & VP)) ^ VP) | X;
        const unsigned long long HN = VP & D0;
        const unsigned long long HP = VN | ~(VP | D0);
        const unsigned long long X2 = (HP << 1) | 1ull;
        VN = X2 & D0;
        VP = (HN << 1) | ~(X2 | D0);

        if (r == l)      { vp0 = VP; vn0 = VN; }
        if (r == l + 32) { vp1 = VP; vn1 = VN; }
    }

    // Phase 2: each lane analyzes its two rows, fully lane-local.
    #pragma unroll 1
    for (int slot = 0; slot < 2; slot++) {
        const int r = l + 32 * slot;
        const unsigned long long vp = slot ? vp1 : vp0;
        const unsigned long long vn = slot ? vn1 : vn0;

        // pass 1: masked min of the row profile
        int d = r;
        int mn = 0x7fffffff;
        #pragma unroll
        for (int c = 0; c < 64; c++) {
            if (c > 0)
                d += (int)((vp >> (c - 1)) & 1ull) - (int)((vn >> (c - 1)) & 1ull);
            if ((mm >> c) & 1ull) mn = min(mn, d);
        }

        // pass 2: distinct vocab among argmin positions + gather-sum
        int   nrep = 0;
        int   reps[64];
        float sum = 0.f;
        d = r;
        #pragma unroll 1
        for (int c = 0; c < 64; c++) {
            if (c > 0)
                d += (int)((vp >> (c - 1)) & 1ull) - (int)((vn >> (c - 1)) & 1ull);
            if (((mm >> c) & 1ull) && d == mn) {
                const int v = tgt_s[c];
                bool dup = false;
                for (int j = 0; j < nrep; j++) dup |= (reps[j] == v);
                if (!dup) { reps[nrep++] = v; sum += gsh[r * 65 + c]; }
            }
        }
        g_m[b * 64 + r]    = nrep;
        g_sumS[b * 64 + r] = sum;
    }
}

// ---------------------------------------------------------------------------
// Kernel B: per-(b,r) row sum over V + closed-form KL loss. One block per row.
// This is the memory-bound kernel (reads outputs once; skips masked rows).
// ---------------------------------------------------------------------------
__global__ void __launch_bounds__(256) loss_kernel(
    const float* __restrict__ outputs,
    const unsigned char* __restrict__ mask)
{
    const int row = blockIdx.x;               // b*64 + r
    if (!mask[row]) {
        if (threadIdx.x == 0) g_loss[row] = 0.f;
        return;
    }

    const float4* p = (const float4*)(outputs + (size_t)row * NV);
    float s = 0.f;
    #pragma unroll 4
    for (int i = threadIdx.x; i < NV / 4; i += 256) {
        const float4 v = p[i];
        s += (v.x + v.y) + (v.z + v.w);
    }

    __shared__ float red[8];
    #pragma unroll
    for (int o = 16; o > 0; o >>= 1)
        s += __shfl_down_sync(0xffffffffu, s, o);
    if ((threadIdx.x & 31) == 0) red[threadIdx.x >> 5] = s;
    __syncthreads();

    if (threadIdx.x == 0) {
        float tot = 0.f;
        #pragma unroll
        for (int w = 0; w < 8; w++) tot += red[w];

        const int   m    = g_m[row];
        const float sumS = g_sumS[row];
        const float einv = 0.36787944117144233f;   // e^-1
        const float D    = (float)m + (float)(NV - m) * einv;
        const float p_hi = 1.0f / D;
        const float p_lo = einv / D;
        const float kl = (float)m * p_hi * logf(p_hi)
                       + (float)(NV - m) * p_lo * logf(p_lo)
                       - (p_lo * tot + (p_hi - p_lo) * sumS);
        g_loss[row] = kl;
    }
}

// ---------------------------------------------------------------------------
// Kernel C: final reduction to scalar. One warp; thread b handles batch b.
// ---------------------------------------------------------------------------
__global__ void __launch_bounds__(32) final_kernel(
    const unsigned char* __restrict__ mask,
    float* __restrict__ out)
{
    const int b = threadIdx.x;   // 0..31
    float w  = 0.f;
    float ls = 0.f;
    #pragma unroll 1
    for (int j = 0; j < 64; j++) {
        w  += (mask[b * 64 + j] != 0) ? 1.f : 0.f;
        ls += g_loss[b * 64 + j];
    }
    float pb = ls / (w + 1e-13f);
    const unsigned nb = __ballot_sync(0xffffffffu, w > 0.f);
    const float n_nonempty = (float)__popc(nb) + 1e-13f;
    #pragma unroll
    for (int o = 16; o > 0; o >>= 1)
        pb += __shfl_down_sync(0xffffffffu, pb, o);
    if (b == 0) out[0] = pb / n_nonempty;
}

extern "C" void kernel_launch(void* const* d_in, const int* in_sizes, int n_in,
                              void* d_out, int out_size)
{
    const float* outputs        = (const float*)d_in[0];
    const int*   output_symbols = (const int*)d_in[1];
    const int*   targets        = (const int*)d_in[2];
    const unsigned char* mask   = (const unsigned char*)d_in[3];

    dp_kernel<<<NB, 32>>>(outputs, output_symbols, targets, mask);
    loss_kernel<<<NB * NP, 256>>>(outputs, mask);
    final_kernel<<<1, 32>>>(mask, (float*)d_out);
}

// round 2
// speedup vs baseline: 1.3601x; 1.3601x over previous
#include <cuda_runtime.h>
#include <cstdint>

#define NB 32
#define NP 64
#define NL 64
#define NV 32000

// scratch (no allocations allowed)
__device__ float g_loss[NB * NP];

// ---------------------------------------------------------------------------
// Fused kernel: one block per (b, r) row of `outputs`.
//   warp 0      : Myers bit-parallel edit-distance DP to row r, argmin truth
//                 set, distinct-vocab dedup, gather sum over the truth set.
//   warps 1..7  : streaming float4 row sum over V (the memory-bound part).
// The DP (~2k cycles of warp-ALU) is fully hidden under the 128KB row stream.
// ---------------------------------------------------------------------------
__global__ void __launch_bounds__(256) fused_kernel(
    const float* __restrict__ outputs,
    const int*   __restrict__ outsym,
    const int*   __restrict__ targets,
    const unsigned char* __restrict__ mask)
{
    const int row = blockIdx.x;          // b*64 + r
    const int b   = row >> 6;
    const int r   = row & 63;

    if (!mask[row]) {                    // masked row contributes 0
        if (threadIdx.x == 0) g_loss[row] = 0.f;
        return;
    }

    __shared__ int    tgt_s[64];
    __shared__ int    sym_s[64];
    __shared__ double red[8];
    __shared__ int    m_sh;
    __shared__ float  sumS_sh;

    const int tid = threadIdx.x;
    const int wid = tid >> 5;
    const int l   = tid & 31;

    if (wid == 0) {
        // ---- metadata (per-batch, L2-hot across the 64 row-blocks) ----
        const int t_lo = targets[b * 64 + l];
        const int t_hi = targets[b * 64 + 32 + l];
        tgt_s[l]      = t_lo;
        tgt_s[32 + l] = t_hi;
        sym_s[l]      = outsym[b * 64 + l];
        sym_s[32 + l] = outsym[b * 64 + 32 + l];
        const unsigned mml = __ballot_sync(0xffffffffu, mask[b * 64 + l] != 0);
        const unsigned mmh = __ballot_sync(0xffffffffu, mask[b * 64 + 32 + l] != 0);
        const unsigned long long mm =
            ((unsigned long long)mmh << 32) | (unsigned long long)mml;
        __syncwarp();

        // ---- Myers bit-vector DP up to row r (pattern = targets[0..62]) ----
        // Invariant after row i: VP/VN bit k = dist[i][k+1] - dist[i][k].
        unsigned long long VP = 0x7FFFFFFFFFFFFFFFull;   // row 0 = arange
        unsigned long long VN = 0ull;
        for (int i = 1; i <= r; i++) {
            const int s = sym_s[i - 1];
            const unsigned eql = __ballot_sync(0xffffffffu, t_lo == s);
            const unsigned eqh = __ballot_sync(0xffffffffu, t_hi == s) & 0x7FFFFFFFu;
            const unsigned long long Eq =
                ((unsigned long long)eqh << 32) | (unsigned long long)eql;
            const unsigned long long X  = Eq | VN;
            const unsigned long long D0 = ((VP + (X & VP)) ^ VP) | X;
            const unsigned long long HN = VP & D0;
            const unsigned long long HP = VN | ~(VP | D0);
            const unsigned long long X2 = (HP << 1) | 1ull;
            VN = X2 & D0;
            VP = (HN << 1) | ~(X2 | D0);
        }

        // ---- row profile: lane l owns columns l and l+32 ----
        const unsigned long long lm0 = (1ull << l) - 1ull;
        const unsigned long long lm1 = (1ull << (l + 32)) - 1ull;
        const int d0 = r + __popcll(VP & lm0) - __popcll(VN & lm0);
        const int d1 = r + __popcll(VP & lm1) - __popcll(VN & lm1);
        const int md0 = ((mm >> l) & 1ull)        ? d0 : 0x7fffffff;
        const int md1 = ((mm >> (l + 32)) & 1ull) ? d1 : 0x7fffffff;

        int mn = min(md0, md1);
        #pragma unroll
        for (int o = 16; o > 0; o >>= 1)
            mn = min(mn, __shfl_xor_sync(0xffffffffu, mn, o));

        const unsigned cm_lo = __ballot_sync(0xffffffffu, md0 == mn);
        const unsigned cm_hi = __ballot_sync(0xffffffffu, md1 == mn);
        const unsigned long long CM =
            ((unsigned long long)cm_hi << 32) | (unsigned long long)cm_lo;

        // ---- dedup: keep column c iff no earlier candidate shares its vocab ----
        bool keep0 = (md0 == mn);
        if (keep0) {
            unsigned long long e = CM & lm0;
            while (e) {
                const int c = __ffsll((long long)e) - 1;
                e &= e - 1;
                if (tgt_s[c] == t_lo) { keep0 = false; break; }
            }
        }
        bool keep1 = (md1 == mn);
        if (keep1) {
            unsigned long long e = CM & lm1;
            while (e) {
                const int c = __ffsll((long long)e) - 1;
                e &= e - 1;
                if (tgt_s[c] == t_hi) { keep1 = false; break; }
            }
        }
        const unsigned k0 = __ballot_sync(0xffffffffu, keep0);
        const unsigned k1 = __ballot_sync(0xffffffffu, keep1);
        const int m = __popc(k0) + __popc(k1);

        // ---- gather sum over the distinct truth set (L2-hot row) ----
        const float* rowp = outputs + (size_t)row * NV;
        float s = 0.f;
        if (keep0) s += __ldg(rowp + t_lo);
        if (keep1) s += __ldg(rowp + t_hi);
        #pragma unroll
        for (int o = 16; o > 0; o >>= 1)
            s += __shfl_xor_sync(0xffffffffu, s, o);

        if (l == 0) { m_sh = m; sumS_sh = s; }
    } else {
        // ---- streaming row sum (Kahan per thread, double reduce) ----
        const float4* p = (const float4*)(outputs + (size_t)row * NV);
        float s = 0.f, comp = 0.f;
        #pragma unroll 4
        for (int i = tid - 32; i < NV / 4; i += 224) {
            const float4 v = p[i];
            const float t = (v.x + v.y) + (v.z + v.w);
            const float y = t - comp;
            const float u = s + y;
            comp = (u - s) - y;
            s = u;
        }
        double ds = (double)s - (double)comp;
        #pragma unroll
        for (int o = 16; o > 0; o >>= 1)
            ds += __shfl_xor_sync(0xffffffffu, ds, o);
        if (l == 0) red[wid] = ds;
    }
    __syncthreads();

    if (tid == 0) {
        double tot = 0.0;
        #pragma unroll
        for (int w = 1; w < 8; w++) tot += red[w];

        const int    m    = m_sh;
        const double sumS = (double)sumS_sh;
        const double einv = 0.36787944117144233;          // e^-1
        const double D    = (double)m + (double)(NV - m) * einv;
        const double phi  = 1.0 / D;
        const double plo  = einv / D;
        const double kl   = (double)m * phi * log(phi)
                          + (double)(NV - m) * plo * log(plo)
                          - (plo * tot + (phi - plo) * sumS);
        g_loss[row] = (float)kl;
    }
}

// ---------------------------------------------------------------------------
// Final reduction to scalar. One warp; thread b handles batch b.
// ---------------------------------------------------------------------------
__global__ void __launch_bounds__(32) final_kernel(
    const unsigned char* __restrict__ mask,
    float* __restrict__ out)
{
    const int b = threadIdx.x;   // 0..31
    double w  = 0.0;
    double ls = 0.0;
    #pragma unroll 1
    for (int j = 0; j < 64; j++) {
        w  += (mask[b * 64 + j] != 0) ? 1.0 : 0.0;
        ls += (double)g_loss[b * 64 + j];
    }
    double pb = ls / (w + 1e-13);
    const unsigned nb = __ballot_sync(0xffffffffu, w > 0.0);
    const double n_nonempty = (double)__popc(nb) + 1e-13;
    #pragma unroll
    for (int o = 16; o > 0; o >>= 1)
        pb += __shfl_xor_sync(0xffffffffu, pb, o);
    if (b == 0) out[0] = (float)(pb / n_nonempty);
}

extern "C" void kernel_launch(void* const* d_in, const int* in_sizes, int n_in,
                              void* d_out, int out_size)
{
    const float* outputs        = (const float*)d_in[0];
    const int*   output_symbols = (const int*)d_in[1];
    const int*   targets        = (const int*)d_in[2];
    const unsigned char* mask   = (const unsigned char*)d_in[3];

    fused_kernel<<<NB * NP, 256>>>(outputs, output_symbols, targets, mask);
    final_kernel<<<1, 32>>>(mask, (float*)d_out);
}

// round 3
// speedup vs baseline: 1.8663x; 1.3722x over previous
#include <cuda_runtime.h>
#include <cstdint>

#define NB 32
#define NP 64
#define NL 64
#define NV 32000
#define NROWS (NB * NP)

// scratch (no allocations allowed)
__device__ float g_loss[NROWS];
__device__ int   g_ticket = 0;

// ---------------------------------------------------------------------------
// Fused kernel: one block per (b, r) row of `outputs`.
//   warp 0      : Myers bit-parallel edit-distance DP to row r, argmin truth
//                 set, distinct-vocab dedup, gather sum over the truth set.
//   warps 1..7  : streaming float4 row sum over V (the memory-bound part).
// The LAST block to finish (threadfence-ticket) does the final reduction
// in-kernel with 256 parallel threads, writing the scalar to d_out.
// ---------------------------------------------------------------------------
__global__ void __launch_bounds__(256) fused_kernel(
    const float* __restrict__ outputs,
    const int*   __restrict__ outsym,
    const int*   __restrict__ targets,
    const unsigned char* __restrict__ mask,
    float* __restrict__ out)
{
    const int row = blockIdx.x;          // b*64 + r
    const int b   = row >> 6;
    const int r   = row & 63;

    const int tid = threadIdx.x;
    const int wid = tid >> 5;
    const int l   = tid & 31;

    __shared__ int    tgt_s[64];
    __shared__ int    sym_s[64];
    __shared__ double red[8];
    __shared__ int    m_sh;
    __shared__ float  sumS_sh;
    __shared__ int    last_sh;

    if (mask[row]) {
        if (wid == 0) {
            // ---- metadata (per-batch, L2-hot across the 64 row-blocks) ----
            const int t_lo = targets[b * 64 + l];
            const int t_hi = targets[b * 64 + 32 + l];
            tgt_s[l]      = t_lo;
            tgt_s[32 + l] = t_hi;
            sym_s[l]      = outsym[b * 64 + l];
            sym_s[32 + l] = outsym[b * 64 + 32 + l];
            const unsigned mml = __ballot_sync(0xffffffffu, mask[b * 64 + l] != 0);
            const unsigned mmh = __ballot_sync(0xffffffffu, mask[b * 64 + 32 + l] != 0);
            const unsigned long long mm =
                ((unsigned long long)mmh << 32) | (unsigned long long)mml;
            __syncwarp();

            // ---- Myers bit-vector DP up to row r (pattern = targets[0..62]) ----
            unsigned long long VP = 0x7FFFFFFFFFFFFFFFull;   // row 0 = arange
            unsigned long long VN = 0ull;
            for (int i = 1; i <= r; i++) {
                const int s = sym_s[i - 1];
                const unsigned eql = __ballot_sync(0xffffffffu, t_lo == s);
                const unsigned eqh = __ballot_sync(0xffffffffu, t_hi == s) & 0x7FFFFFFFu;
                const unsigned long long Eq =
                    ((unsigned long long)eqh << 32) | (unsigned long long)eql;
                const unsigned long long X  = Eq | VN;
                const unsigned long long D0 = ((VP + (X & VP)) ^ VP) | X;
                const unsigned long long HN = VP & D0;
                const unsigned long long HP = VN | ~(VP | D0);
                const unsigned long long X2 = (HP << 1) | 1ull;
                VN = X2 & D0;
                VP = (HN << 1) | ~(X2 | D0);
            }

            // ---- row profile: lane l owns columns l and l+32 ----
            const unsigned long long lm0 = (1ull << l) - 1ull;
            const unsigned long long lm1 = (1ull << (l + 32)) - 1ull;
            const int d0 = r + __popcll(VP & lm0) - __popcll(VN & lm0);
            const int d1 = r + __popcll(VP & lm1) - __popcll(VN & lm1);
            const int md0 = ((mm >> l) & 1ull)        ? d0 : 0x7fffffff;
            const int md1 = ((mm >> (l + 32)) & 1ull) ? d1 : 0x7fffffff;

            int mn = min(md0, md1);
            #pragma unroll
            for (int o = 16; o > 0; o >>= 1)
                mn = min(mn, __shfl_xor_sync(0xffffffffu, mn, o));

            const unsigned cm_lo = __ballot_sync(0xffffffffu, md0 == mn);
            const unsigned cm_hi = __ballot_sync(0xffffffffu, md1 == mn);
            const unsigned long long CM =
                ((unsigned long long)cm_hi << 32) | (unsigned long long)cm_lo;

            // ---- dedup: keep col c iff no earlier candidate has same vocab ----
            bool keep0 = (md0 == mn);
            if (keep0) {
                unsigned long long e = CM & lm0;
                while (e) {
                    const int c = __ffsll((long long)e) - 1;
                    e &= e - 1;
                    if (tgt_s[c] == t_lo) { keep0 = false; break; }
                }
            }
            bool keep1 = (md1 == mn);
            if (keep1) {
                unsigned long long e = CM & lm1;
                while (e) {
                    const int c = __ffsll((long long)e) - 1;
                    e &= e - 1;
                    if (tgt_s[c] == t_hi) { keep1 = false; break; }
                }
            }
            const unsigned k0 = __ballot_sync(0xffffffffu, keep0);
            const unsigned k1 = __ballot_sync(0xffffffffu, keep1);
            const int m = __popc(k0) + __popc(k1);

            // ---- gather sum over distinct truth set (L2-hot row) ----
            const float* rowp = outputs + (size_t)row * NV;
            float s = 0.f;
            if (keep0) s += __ldg(rowp + t_lo);
            if (keep1) s += __ldg(rowp + t_hi);
            #pragma unroll
            for (int o = 16; o > 0; o >>= 1)
                s += __shfl_xor_sync(0xffffffffu, s, o);

            if (l == 0) { m_sh = m; sumS_sh = s; }
        } else {
            // ---- streaming row sum (Kahan per thread, double reduce) ----
            const float4* p = (const float4*)(outputs + (size_t)row * NV);
            float s = 0.f, comp = 0.f;
            #pragma unroll 4
            for (int i = tid - 32; i < NV / 4; i += 224) {
                const float4 v = p[i];
                const float t = (v.x + v.y) + (v.z + v.w);
                const float y = t - comp;
                const float u = s + y;
                comp = (u - s) - y;
                s = u;
            }
            double ds = (double)s - (double)comp;
            #pragma unroll
            for (int o = 16; o > 0; o >>= 1)
                ds += __shfl_xor_sync(0xffffffffu, ds, o);
            if (l == 0) red[wid] = ds;
        }
        __syncthreads();

        if (tid == 0) {
            double tot = 0.0;
            #pragma unroll
            for (int w = 1; w < 8; w++) tot += red[w];

            const int    m    = m_sh;
            const double sumS = (double)sumS_sh;
            const double einv = 0.36787944117144233;          // e^-1
            const double D    = (double)m + (double)(NV - m) * einv;
            const double phi  = 1.0 / D;
            const double plo  = einv / D;
            const double kl   = (double)m * phi * log(phi)
                              + (double)(NV - m) * plo * log(plo)
                              - (plo * tot + (phi - plo) * sumS);
            g_loss[row] = (float)kl;
        }
    } else {
        if (tid == 0) g_loss[row] = 0.f;
    }

    // ---- threadfence-ticket: last block does the final reduction ----
    if (tid == 0) {
        __threadfence();
        const int t = atomicAdd(&g_ticket, 1);
        last_sh = (t == NROWS - 1);
    }
    __syncthreads();

    if (last_sh) {
        __shared__ double pb_sh[32];
        __shared__ int    ne_sh[32];

        // thread t: batch bb = t>>3, chunk sub = t&7 (8 elements each)
        const int bb  = tid >> 3;
        const int sub = tid & 7;
        double ls = 0.0, w = 0.0;
        #pragma unroll
        for (int j = 0; j < 8; j++) {
            const int idx = bb * 64 + sub * 8 + j;
            ls += (double)g_loss[idx];
            w  += (mask[idx] != 0) ? 1.0 : 0.0;
        }
        // reduce across the 8 sub-chunks (aligned segments within a warp)
        #pragma unroll
        for (int o = 4; o > 0; o >>= 1) {
            ls += __shfl_xor_sync(0xffffffffu, ls, o);
            w  += __shfl_xor_sync(0xffffffffu, w,  o);
        }
        if (sub == 0) {
            pb_sh[bb] = ls / (w + 1e-13);
            ne_sh[bb] = (w > 0.0) ? 1 : 0;
        }
        __syncthreads();

        if (tid < 32) {
            double pb = pb_sh[tid];
            int    ne = ne_sh[tid];
            #pragma unroll
            for (int o = 16; o > 0; o >>= 1) {
                pb += __shfl_xor_sync(0xffffffffu, pb, o);
                ne += __shfl_xor_sync(0xffffffffu, ne, o);
            }
            if (tid == 0) {
                out[0] = (float)(pb / ((double)ne + 1e-13));
                g_ticket = 0;           // reset for next graph replay
            }
        }
    }
}

extern "C" void kernel_launch(void* const* d_in, const int* in_sizes, int n_in,
                              void* d_out, int out_size)
{
    const float* outputs        = (const float*)d_in[0];
    const int*   output_symbols = (const int*)d_in[1];
    const int*   targets        = (const int*)d_in[2];
    const unsigned char* mask   = (const unsigned char*)d_in[3];

    fused_kernel<<<NROWS, 256>>>(outputs, output_symbols, targets, mask,
                                 (float*)d_out);
}

// round 4
// speedup vs baseline: 2.0141x; 1.0792x over previous
#include <cuda_runtime.h>
#include <cstdint>

#define NB 32
#define NP 64
#define NL 64
#define NV 32000
#define NROWS (NB * NP)
#define GRID_X 1216          // 152 SMs * 8 blocks/SM -> single resident wave

// scratch (no allocations allowed)
__device__ float g_loss[NROWS];
__device__ int   g_ctr    = 0;   // work-stealing row counter
__device__ int   g_ticket = 0;   // last-block-finishes ticket

// ---------------------------------------------------------------------------
// Fused persistent kernel. Blocks steal rows (b,r) from g_ctr.
//   warp 0      : Myers bit-parallel edit-distance DP to row r, argmin truth
//                 set, distinct-vocab dedup, gather sum over the truth set.
//   warps 1..7  : streaming float4 row sum over V (the memory-bound part).
// Last block (ticket) reduces g_loss -> scalar and resets counters.
// ---------------------------------------------------------------------------
__global__ void __launch_bounds__(256) fused_kernel(
    const float* __restrict__ outputs,
    const int*   __restrict__ outsym,
    const int*   __restrict__ targets,
    const unsigned char* __restrict__ mask,
    float* __restrict__ out)
{
    const int tid = threadIdx.x;
    const int wid = tid >> 5;
    const int l   = tid & 31;

    __shared__ int    s_row;
    __shared__ int    tgt_s[64];
    __shared__ int    sym_s[64];
    __shared__ double red[8];
    __shared__ int    m_sh;
    __shared__ float  sumS_sh;
    __shared__ int    last_sh;

    for (;;) {
        if (tid == 0) s_row = atomicAdd(&g_ctr, 1);
        __syncthreads();
        const int row = s_row;
        if (row >= NROWS) break;

        const int b = row >> 6;
        const int r = row & 63;

        if (mask[row]) {
            if (wid == 0) {
                // ---- metadata (per-batch, L2-hot) ----
                const int t_lo = targets[b * 64 + l];
                const int t_hi = targets[b * 64 + 32 + l];
                tgt_s[l]      = t_lo;
                tgt_s[32 + l] = t_hi;
                sym_s[l]      = outsym[b * 64 + l];
                sym_s[32 + l] = outsym[b * 64 + 32 + l];
                const unsigned mml = __ballot_sync(0xffffffffu, mask[b * 64 + l] != 0);
                const unsigned mmh = __ballot_sync(0xffffffffu, mask[b * 64 + 32 + l] != 0);
                const unsigned long long mm =
                    ((unsigned long long)mmh << 32) | (unsigned long long)mml;
                __syncwarp();

                // ---- Myers bit-vector DP up to row r (pattern = targets[0..62]) ----
                unsigned long long VP = 0x7FFFFFFFFFFFFFFFull;   // row 0 = arange
                unsigned long long VN = 0ull;
                for (int i = 1; i <= r; i++) {
                    const int s = sym_s[i - 1];
                    const unsigned eql = __ballot_sync(0xffffffffu, t_lo == s);
                    const unsigned eqh = __ballot_sync(0xffffffffu, t_hi == s) & 0x7FFFFFFFu;
                    const unsigned long long Eq =
                        ((unsigned long long)eqh << 32) | (unsigned long long)eql;
                    const unsigned long long X  = Eq | VN;
                    const unsigned long long D0 = ((VP + (X & VP)) ^ VP) | X;
                    const unsigned long long HN = VP & D0;
                    const unsigned long long HP = VN | ~(VP | D0);
                    const unsigned long long X2 = (HP << 1) | 1ull;
                    VN = X2 & D0;
                    VP = (HN << 1) | ~(X2 | D0);
                }

                // ---- row profile: lane l owns columns l and l+32 ----
                const unsigned long long lm0 = (1ull << l) - 1ull;
                const unsigned long long lm1 = (1ull << (l + 32)) - 1ull;
                const int d0 = r + __popcll(VP & lm0) - __popcll(VN & lm0);
                const int d1 = r + __popcll(VP & lm1) - __popcll(VN & lm1);
                const int md0 = ((mm >> l) & 1ull)        ? d0 : 0x7fffffff;
                const int md1 = ((mm >> (l + 32)) & 1ull) ? d1 : 0x7fffffff;

                int mn = min(md0, md1);
                #pragma unroll
                for (int o = 16; o > 0; o >>= 1)
                    mn = min(mn, __shfl_xor_sync(0xffffffffu, mn, o));

                const unsigned cm_lo = __ballot_sync(0xffffffffu, md0 == mn);
                const unsigned cm_hi = __ballot_sync(0xffffffffu, md1 == mn);
                const unsigned long long CM =
                    ((unsigned long long)cm_hi << 32) | (unsigned long long)cm_lo;

                // ---- dedup: keep col c iff no earlier candidate has same vocab ----
                bool keep0 = (md0 == mn);
                if (keep0) {
                    unsigned long long e = CM & lm0;
                    while (e) {
                        const int c = __ffsll((long long)e) - 1;
                        e &= e - 1;
                        if (tgt_s[c] == t_lo) { keep0 = false; break; }
                    }
                }
                bool keep1 = (md1 == mn);
                if (keep1) {
                    unsigned long long e = CM & lm1;
                    while (e) {
                        const int c = __ffsll((long long)e) - 1;
                        e &= e - 1;
                        if (tgt_s[c] == t_hi) { keep1 = false; break; }
                    }
                }
                const unsigned k0 = __ballot_sync(0xffffffffu, keep0);
                const unsigned k1 = __ballot_sync(0xffffffffu, keep1);
                const int m = __popc(k0) + __popc(k1);

                // ---- gather sum over distinct truth set (L2-hot row) ----
                const float* rowp = outputs + (size_t)row * NV;
                float s = 0.f;
                if (keep0) s += __ldg(rowp + t_lo);
                if (keep1) s += __ldg(rowp + t_hi);
                #pragma unroll
                for (int o = 16; o > 0; o >>= 1)
                    s += __shfl_xor_sync(0xffffffffu, s, o);

                if (l == 0) { m_sh = m; sumS_sh = s; }
            } else {
                // ---- streaming row sum (Kahan per thread, double reduce) ----
                const float4* p = (const float4*)(outputs + (size_t)row * NV);
                float s = 0.f, comp = 0.f;
                #pragma unroll 8
                for (int i = tid - 32; i < NV / 4; i += 224) {
                    const float4 v = p[i];
                    const float t = (v.x + v.y) + (v.z + v.w);
                    const float y = t - comp;
                    const float u = s + y;
                    comp = (u - s) - y;
                    s = u;
                }
                double ds = (double)s - (double)comp;
                #pragma unroll
                for (int o = 16; o > 0; o >>= 1)
                    ds += __shfl_xor_sync(0xffffffffu, ds, o);
                if (l == 0) red[wid] = ds;
            }
            __syncthreads();

            if (tid == 0) {
                double tot = 0.0;
                #pragma unroll
                for (int w = 1; w < 8; w++) tot += red[w];

                const int    m    = m_sh;
                const double sumS = (double)sumS_sh;
                const double einv = 0.36787944117144233;          // e^-1
                const double D    = (double)m + (double)(NV - m) * einv;
                const double phi  = 1.0 / D;
                const double plo  = einv / D;
                const double kl   = (double)m * phi * log(phi)
                                  + (double)(NV - m) * plo * log(plo)
                                  - (plo * tot + (phi - plo) * sumS);
                g_loss[row] = (float)kl;
            }
        } else {
            if (tid == 0) g_loss[row] = 0.f;
        }
        __syncthreads();   // protects s_row reuse next iteration
    }

    // ---- threadfence-ticket: last block does the final reduction ----
    if (tid == 0) {
        __threadfence();
        const int t = atomicAdd(&g_ticket, 1);
        last_sh = (t == GRID_X - 1);
    }
    __syncthreads();

    if (last_sh) {
        __shared__ double pb_sh[32];
        __shared__ int    ne_sh[32];

        // thread t: batch bb = t>>3, chunk sub = t&7 (8 elements each)
        const int bb  = tid >> 3;
        const int sub = tid & 7;
        double ls = 0.0, w = 0.0;
        #pragma unroll
        for (int j = 0; j < 8; j++) {
            const int idx = bb * 64 + sub * 8 + j;
            ls += (double)g_loss[idx];
            w  += (mask[idx] != 0) ? 1.0 : 0.0;
        }
        #pragma unroll
        for (int o = 4; o > 0; o >>= 1) {
            ls += __shfl_xor_sync(0xffffffffu, ls, o);
            w  += __shfl_xor_sync(0xffffffffu, w,  o);
        }
        if (sub == 0) {
            pb_sh[bb] = ls / (w + 1e-13);
            ne_sh[bb] = (w > 0.0) ? 1 : 0;
        }
        __syncthreads();

        if (tid < 32) {
            double pb = pb_sh[tid];
            int    ne = ne_sh[tid];
            #pragma unroll
            for (int o = 16; o > 0; o >>= 1) {
                pb += __shfl_xor_sync(0xffffffffu, pb, o);
                ne += __shfl_xor_sync(0xffffffffu, ne, o);
            }
            if (tid == 0) {
                out[0] = (float)(pb / ((double)ne + 1e-13));
                g_ticket = 0;           // reset for next graph replay
                g_ctr    = 0;
            }
        }
    }
}

extern "C" void kernel_launch(void* const* d_in, const int* in_sizes, int n_in,
                              void* d_out, int out_size)
{
    const float* outputs        = (const float*)d_in[0];
    const int*   output_symbols = (const int*)d_in[1];
    const int*   targets        = (const int*)d_in[2];
    const unsigned char* mask   = (const unsigned char*)d_in[3];

    fused_kernel<<<GRID_X, 256>>>(outputs, output_symbols, targets, mask,
                                  (float*)d_out);
}